// round 16
// baseline (speedup 1.0000x reference)
#include <cuda_runtime.h>
#include <cuda_bf16.h>
#include <cuda_fp16.h>

#define NN 10000
#define IN_F 128
#define OUT_F 64
#define EDGES 320000
#define ALPHA 0.2f
#define GEMM_BM 64
#define GEMM_BLOCKS ((NN + GEMM_BM - 1) / GEMM_BM)   // 157
#define SCAT_BLOCKS 287                               // 157+287 = 444 = 148*3 (one wave)
#define HS_LD 132                                     // row stride (pad, 16B-aligned)
#define FUSED_SMEM ((IN_F * OUT_F + GEMM_BM * HS_LD) * (int)sizeof(float))  // 66560 B
#define CAP 128        // bucket capacity; max degree of Poisson(32) over 10k rows ~ 56

// ---------------- scratch (device globals; zero-initialized at load) --------
__device__ int     g_deg[NN];                // invariant: zero at kernel_launch entry
__device__ int     g_cols[NN * CAP];         // 5.12 MB padded buckets
__device__ __half2 g_Whh[NN * (OUT_F / 2)];  // 1.28 MB fp16 Wh (gather source)
__device__ float   g_s1[NN];
__device__ float   g_s2[NN];
__device__ float   g_meanpart[GEMM_BLOCKS * OUT_F];

// ---------------- helpers ---------------------------------------------------
__device__ __forceinline__ int edge_src(const void* p, int e, int is64) {
    return is64 ? (int)((const long long*)p)[e] : ((const int*)p)[e];
}
__device__ __forceinline__ int edge_dst(const void* p, int e, int is64) {
    return is64 ? (int)((const long long*)p)[EDGES + e] : ((const int*)p)[EDGES + e];
}
__device__ __forceinline__ float elu_f(float x) {
    return x > 0.f ? x : expm1f(x);
}

// ---------------- 1. fused: GEMM(+s1/s2+mean) blocks || scatter blocks ------
// blockIdx < GEMM_BLOCKS : one 64-row tile of Wh = h @ W, fused epilogues.
//   Wh is stored ONLY as fp16 (gather consumes fp16; s1/s2/mean come straight
//   from the fp32 accumulators).
// blockIdx >= GEMM_BLOCKS: grid-stride bucket scatter of the edge list.
__global__ void fused_kernel(const float* __restrict__ h, const float* __restrict__ W,
                             const float* __restrict__ a, const void* __restrict__ ei) {
    int t = threadIdx.x;

    if (blockIdx.x >= GEMM_BLOCKS) {
        // ------------------- scatter role --------------------------------
        // dtype detect: warp 0 reads the FIRST 32 int64s (L2 broadcast).
        // int64 data: all are src ids in [0, NN). int32 data: each read packs
        // two node ids -> looks valid only if high word == 0 (P = 1e-4 each);
        // P(all 32 look valid) = 1e-128 -> detection certain.
        __shared__ int s_is64;
        if (t < 32) {
            const long long* p = (const long long*)ei;
            long long v = p[t];
            bool bad = (v < 0 || v >= NN);
            unsigned m = __ballot_sync(0xFFFFFFFFu, bad);
            if (t == 0) s_is64 = (m == 0u) ? 1 : 0;
        }
        __syncthreads();
        int is64 = s_is64;
        int sbid = blockIdx.x - GEMM_BLOCKS;
        for (int e = sbid * 256 + t; e < EDGES; e += SCAT_BLOCKS * 256) {
            int s = edge_src(ei, e, is64);
            int d = edge_dst(ei, e, is64);
            int pos = atomicAdd(&g_deg[s], 1);
            if (pos < CAP) g_cols[s * CAP + pos] = d;  // clamp (never hit in practice)
        }
        return;
    }

    // ---------------------- gemm role ------------------------------------
    extern __shared__ float smem[];
    float* Ws = smem;                        // [128][64]  32 KB, [k][c]
    float* hs = smem + IN_F * OUT_F;         // [64][132]  33.8 KB, [r][k] row-major
    int row0 = blockIdx.x * GEMM_BM;

    for (int i = t; i < IN_F * OUT_F; i += 256) Ws[i] = W[i];
    // coalesced float4 global loads, conflict-free float4 smem stores
    for (int i = t; i < GEMM_BM * (IN_F / 4); i += 256) {
        int r = i >> 5, cq = i & 31;         // r in [0,64), cq in [0,32)
        int gr = row0 + r;
        float4 v = make_float4(0.f, 0.f, 0.f, 0.f);
        if (gr < NN) v = *(const float4*)&h[gr * IN_F + cq * 4];
        *(float4*)&hs[r * HS_LD + cq * 4] = v;
    }
    __syncthreads();

    int tr = t >> 4, tc = t & 15;
    int rbase = tr * 4, cbase = tc * 4;
    const float* h0 = &hs[(rbase + 0) * HS_LD];
    const float* h1 = &hs[(rbase + 1) * HS_LD];
    const float* h2 = &hs[(rbase + 2) * HS_LD];
    const float* h3 = &hs[(rbase + 3) * HS_LD];
    float acc[4][4] = {};
#pragma unroll 4
    for (int k = 0; k < IN_F; k++) {
        float4 wv = *(const float4*)&Ws[k * OUT_F + cbase];
        float a0v = h0[k], a1v = h1[k], a2v = h2[k], a3v = h3[k];  // broadcast LDS
        acc[0][0] += a0v * wv.x; acc[0][1] += a0v * wv.y; acc[0][2] += a0v * wv.z; acc[0][3] += a0v * wv.w;
        acc[1][0] += a1v * wv.x; acc[1][1] += a1v * wv.y; acc[1][2] += a1v * wv.z; acc[1][3] += a1v * wv.w;
        acc[2][0] += a2v * wv.x; acc[2][1] += a2v * wv.y; acc[2][2] += a2v * wv.z; acc[2][3] += a2v * wv.w;
        acc[3][0] += a3v * wv.x; acc[3][1] += a3v * wv.y; acc[3][2] += a3v * wv.z; acc[3][3] += a3v * wv.w;
    }

    // store Wh as fp16 (two half2 per row of 4 columns)
#pragma unroll
    for (int j = 0; j < 4; j++) {
        int gr = row0 + rbase + j;
        if (gr < NN) {
            __half2 p01 = __float22half2_rn(make_float2(acc[j][0], acc[j][1]));
            __half2 p23 = __float22half2_rn(make_float2(acc[j][2], acc[j][3]));
            g_Whh[gr * (OUT_F / 2) + (cbase >> 1)]     = p01;
            g_Whh[gr * (OUT_F / 2) + (cbase >> 1) + 1] = p23;
        }
    }

    // ---- fused s1/s2: s1[r] = Wh[r,:]·a[0:64], s2[r] = Wh[r,:]·a[64:128] ----
    float av1[4], av2[4];
#pragma unroll
    for (int c = 0; c < 4; c++) { av1[c] = a[cbase + c]; av2[c] = a[64 + cbase + c]; }
#pragma unroll
    for (int j = 0; j < 4; j++) {
        float p1 = acc[j][0]*av1[0] + acc[j][1]*av1[1] + acc[j][2]*av1[2] + acc[j][3]*av1[3];
        float p2 = acc[j][0]*av2[0] + acc[j][1]*av2[1] + acc[j][2]*av2[2] + acc[j][3]*av2[3];
        // xor-reduce over the 16 col-group lanes (xor of bits 0..3 stays in row group)
#pragma unroll
        for (int off = 8; off > 0; off >>= 1) {
            p1 += __shfl_xor_sync(0xFFFFFFFFu, p1, off);
            p2 += __shfl_xor_sync(0xFFFFFFFFu, p2, off);
        }
        int gr = row0 + rbase + j;
        if (tc == 0 && gr < NN) { g_s1[gr] = p1; g_s2[gr] = p2; }
    }

    // ---- fused column-sum partials (zero-degree softmax fallback) ----------
    __syncthreads();                          // done with hs: reuse as scratch
    float* cs = hs;                           // 256*4 floats = 4 KB
    {
        float4 colsum = make_float4(acc[0][0] + acc[1][0] + acc[2][0] + acc[3][0],
                                    acc[0][1] + acc[1][1] + acc[2][1] + acc[3][1],
                                    acc[0][2] + acc[1][2] + acc[2][2] + acc[3][2],
                                    acc[0][3] + acc[1][3] + acc[2][3] + acc[3][3]);
        *(float4*)&cs[t * 4] = colsum;
    }
    __syncthreads();
    if (t < 64) {
        int tcq = t >> 2, ccq = t & 3;
        float s = 0.f;
#pragma unroll
        for (int tr2 = 0; tr2 < 16; tr2++) s += cs[(tr2 * 16 + tcq) * 4 + ccq];
        g_meanpart[blockIdx.x * OUT_F + t] = s;
    }
}

// ---------------- 2. warp-per-row: 2-chunk prefetch dedup + unroll-8 gather -
// Phase A: bucket ids AND s2 values for up to TWO chunks are loaded up front
// (all global latency overlapped once); dedup/stage then runs on LDS only.
// Chunks >= 2 (P ~ 1e-6) fall back to the serial path. Phase B: proven R14
// flat unroll-8 gather: per slot 1 LDS.64 + 1 LDG.32 (half2) + cvt + 2 FFMA.
__global__ void __launch_bounds__(256, 8) row_kernel(float* __restrict__ out) {
    __shared__ int    sc[8][CAP];             // per-warp real dst ids (dedup)  4 KB
    __shared__ float2 swc[8][CAP];            // per-warp (w, half2 row base)   8 KB
    int wrp = threadIdx.x >> 5;
    int gtid = blockIdx.x * blockDim.x + threadIdx.x;
    int row = gtid >> 5;                      // uniform across the warp
    int lane = gtid & 31;
    if (row >= NN) return;

    int deg = g_deg[row];
    if (deg > CAP) deg = CAP;
    __syncwarp();
    if (lane == 0) g_deg[row] = 0;            // restore zero-invariant for replay

    const int* bucket = &g_cols[row * CAP];
    int*    scw  = sc[wrp];
    float2* swcw = swc[wrp];
    float s1r = g_s1[row];
    float swl = 0.f;
    int nch = (deg + 31) >> 5;

    // -------- Phase A: prefetch both chunks, then dedup + stage -------------
    // chunk 0 prefetch
    bool v0 = lane < deg;
    int  c0 = v0 ? bucket[lane] : -(lane + 1);        // unique sentinels
    // chunk 1 prefetch (issued before ANY processing -> latency overlapped)
    bool have1 = nch > 1;
    bool v1 = have1 && (32 + lane) < deg;
    int  c1 = v1 ? bucket[32 + lane] : -(lane + 33);  // distinct sentinel range
    float s20 = g_s2[c0 < 0 ? 0 : c0];
    float s21 = have1 ? g_s2[c1 < 0 ? 0 : c1] : 0.f;

    {   // ---- process chunk 0 (within-chunk dedup only) ----
        unsigned peers = __match_any_sync(0xFFFFFFFFu, c0);
        bool dup = (peers & ((1u << lane) - 1u)) != 0u;
        float w = 0.f;
        bool live = v0 && !dup;
        if (live) {
            float x = s1r + s20;
            float lr = x > 0.f ? x : ALPHA * x;       // leaky relu
            w = __expf(lr);                           // rel err ~1e-6 << budget
            swl += w;
        }
        scw[lane]  = c0;
        swcw[lane] = make_float2(w, __int_as_float(live ? c0 * (OUT_F / 2) : 0));
        __syncwarp();
    }
    if (have1) {  // ---- process chunk 1 (cross compare vs chunk 0 via LDS) ----
        bool dup = false;
        for (int q = 0; q < 32; q++)                  // break-free: pipelined LDS
            if (scw[q] == c1) dup = true;
        unsigned peers = __match_any_sync(0xFFFFFFFFu, c1);
        if (peers & ((1u << lane) - 1u)) dup = true;
        float w = 0.f;
        bool live = v1 && !dup;
        if (live) {
            float x = s1r + s21;
            float lr = x > 0.f ? x : ALPHA * x;
            w = __expf(lr);
            swl += w;
        }
        scw[32 + lane]  = c1;
        swcw[32 + lane] = make_float2(w, __int_as_float(live ? c1 * (OUT_F / 2) : 0));
        __syncwarp();
    }
    // ---- chunks >= 2: P ~ 1e-6, serial fallback ----
    for (int ch = 2; ch < nch; ch++) {
        int p0 = ch << 5;
        int p = p0 + lane;
        bool valid = p < deg;
        int c = valid ? bucket[p] : -(lane + 1 + p0);
        float s2v = g_s2[c < 0 ? 0 : c];
        bool dup = false;
        for (int q = 0; q < p0; q++)
            if (scw[q] == c) dup = true;
        unsigned peers = __match_any_sync(0xFFFFFFFFu, c);
        if (peers & ((1u << lane) - 1u)) dup = true;
        float w = 0.f;
        bool live = valid && !dup;
        if (live) {
            float x = s1r + s2v;
            float lr = x > 0.f ? x : ALPHA * x;
            w = __expf(lr);
            swl += w;
        }
        scw[p]  = c;
        swcw[p] = make_float2(w, __int_as_float(live ? c * (OUT_F / 2) : 0));
        __syncwarp();
    }

    // -------- Phase B: flat branch-free unroll-8 fp16 gather (R14) ----------
    float a0 = 0.f, a1 = 0.f;
#pragma unroll 8
    for (int j = 0; j < deg; j++) {
        float2 wc = swcw[j];                          // one broadcast LDS.64
        int base = __float_as_int(wc.y);              // precomputed half2 row base
        float2 v = __half22float2(g_Whh[base + lane]);  // LDG.32, cols 2l,2l+1
        a0 += wc.x * v.x;
        a1 += wc.x * v.y;
    }

    float sw = swl;
#pragma unroll
    for (int off = 16; off > 0; off >>= 1)
        sw += __shfl_xor_sync(0xFFFFFFFFu, sw, off);

    if (deg == 0) {
        // softmax over an all -inf row is uniform -> h' = column mean of Wh
        float m0 = 0.f, m1 = 0.f;
        for (int b = 0; b < GEMM_BLOCKS; b++) {
            m0 += g_meanpart[b * OUT_F + 2 * lane];
            m1 += g_meanpart[b * OUT_F + 2 * lane + 1];
        }
        a0 = m0 / (float)NN;
        a1 = m1 / (float)NN;
        sw = 1.f;
    }
    float inv = 1.f / sw;
    float2 r = make_float2(elu_f(a0 * inv), elu_f(a1 * inv));
    *(float2*)&out[row * OUT_F + 2 * lane] = r;
}

// ---------------- launch ----------------------------------------------------
extern "C" void kernel_launch(void* const* d_in, const int* in_sizes, int n_in,
                              void* d_out, int out_size) {
    const float* h  = (const float*)d_in[0];
    const void*  ei = d_in[1];
    const float* W  = (const float*)d_in[2];
    const float* a  = (const float*)d_in[3];
    float* out = (float*)d_out;

    // opt into >48KB dynamic smem (idempotent, graph-capture-safe)
    cudaFuncSetAttribute(fused_kernel, cudaFuncAttributeMaxDynamicSharedMemorySize,
                         FUSED_SMEM);

    fused_kernel<<<GEMM_BLOCKS + SCAT_BLOCKS, 256, FUSED_SMEM>>>(h, W, a, ei);
    row_kernel<<<(NN * 32 + 255) / 256, 256>>>(out);
}

// round 17
// speedup vs baseline: 1.0606x; 1.0606x over previous
#include <cuda_runtime.h>
#include <cuda_bf16.h>
#include <cuda_fp16.h>

#define NN 10000
#define IN_F 128
#define OUT_F 64
#define EDGES 320000
#define ALPHA 0.2f
#define GEMM_BM 64
#define GEMM_BLOCKS ((NN + GEMM_BM - 1) / GEMM_BM)   // 157
#define SCAT_BLOCKS 287                               // 157+287 = 444 = 148*3 (one wave)
#define HS_LD 132                                     // row stride (pad, 16B-aligned)
#define FUSED_SMEM ((IN_F * OUT_F + GEMM_BM * HS_LD) * (int)sizeof(float))  // 66560 B
#define CAP 128        // bucket capacity; max degree of Poisson(32) over 10k rows ~ 56

// ---------------- scratch (device globals; zero-initialized at load) --------
__device__ int     g_deg[NN];                // invariant: zero at kernel_launch entry
__device__ int     g_cols[NN * CAP];         // 5.12 MB padded buckets
__device__ __half2 g_Whh[NN * (OUT_F / 2)];  // 1.28 MB fp16 Wh (gather source)
__device__ float   g_s1[NN];
__device__ float   g_s2[NN];
__device__ float   g_meanpart[GEMM_BLOCKS * OUT_F];

// ---------------- helpers ---------------------------------------------------
__device__ __forceinline__ int edge_src(const void* p, int e, int is64) {
    return is64 ? (int)((const long long*)p)[e] : ((const int*)p)[e];
}
__device__ __forceinline__ int edge_dst(const void* p, int e, int is64) {
    return is64 ? (int)((const long long*)p)[EDGES + e] : ((const int*)p)[EDGES + e];
}
__device__ __forceinline__ float elu_f(float x) {
    return x > 0.f ? x : expm1f(x);
}

// ---------------- 1. fused: GEMM(+s1/s2+mean) blocks || scatter blocks ------
// blockIdx < GEMM_BLOCKS : one 64-row tile of Wh = h @ W, fused epilogues.
//   Wh is stored ONLY as fp16 (gather consumes fp16; s1/s2/mean come straight
//   from the fp32 accumulators).
// blockIdx >= GEMM_BLOCKS: grid-stride bucket scatter of the edge list.
__global__ void fused_kernel(const float* __restrict__ h, const float* __restrict__ W,
                             const float* __restrict__ a, const void* __restrict__ ei) {
    int t = threadIdx.x;

    if (blockIdx.x >= GEMM_BLOCKS) {
        // ------------------- scatter role --------------------------------
        // dtype detect: warp 0 reads the FIRST 32 int64s (L2 broadcast).
        // int64 data: all are src ids in [0, NN). int32 data: each read packs
        // two node ids -> looks valid only if high word == 0 (P = 1e-4 each);
        // P(all 32 look valid) = 1e-128 -> detection certain.
        __shared__ int s_is64;
        if (t < 32) {
            const long long* p = (const long long*)ei;
            long long v = p[t];
            bool bad = (v < 0 || v >= NN);
            unsigned m = __ballot_sync(0xFFFFFFFFu, bad);
            if (t == 0) s_is64 = (m == 0u) ? 1 : 0;
        }
        __syncthreads();
        int is64 = s_is64;
        int sbid = blockIdx.x - GEMM_BLOCKS;
        for (int e = sbid * 256 + t; e < EDGES; e += SCAT_BLOCKS * 256) {
            int s = edge_src(ei, e, is64);
            int d = edge_dst(ei, e, is64);
            int pos = atomicAdd(&g_deg[s], 1);
            if (pos < CAP) g_cols[s * CAP + pos] = d;  // clamp (never hit in practice)
        }
        return;
    }

    // ---------------------- gemm role ------------------------------------
    extern __shared__ float smem[];
    float* Ws = smem;                        // [128][64]  32 KB, [k][c]
    float* hs = smem + IN_F * OUT_F;         // [64][132]  33.8 KB, [r][k] row-major
    int row0 = blockIdx.x * GEMM_BM;

    for (int i = t; i < IN_F * OUT_F; i += 256) Ws[i] = W[i];
    // coalesced float4 global loads, conflict-free float4 smem stores
    for (int i = t; i < GEMM_BM * (IN_F / 4); i += 256) {
        int r = i >> 5, cq = i & 31;         // r in [0,64), cq in [0,32)
        int gr = row0 + r;
        float4 v = make_float4(0.f, 0.f, 0.f, 0.f);
        if (gr < NN) v = *(const float4*)&h[gr * IN_F + cq * 4];
        *(float4*)&hs[r * HS_LD + cq * 4] = v;
    }
    __syncthreads();

    int tr = t >> 4, tc = t & 15;
    int rbase = tr * 4, cbase = tc * 4;
    const float* h0 = &hs[(rbase + 0) * HS_LD];
    const float* h1 = &hs[(rbase + 1) * HS_LD];
    const float* h2 = &hs[(rbase + 2) * HS_LD];
    const float* h3 = &hs[(rbase + 3) * HS_LD];
    float acc[4][4] = {};
#pragma unroll 4
    for (int k = 0; k < IN_F; k++) {
        float4 wv = *(const float4*)&Ws[k * OUT_F + cbase];
        float a0v = h0[k], a1v = h1[k], a2v = h2[k], a3v = h3[k];  // broadcast LDS
        acc[0][0] += a0v * wv.x; acc[0][1] += a0v * wv.y; acc[0][2] += a0v * wv.z; acc[0][3] += a0v * wv.w;
        acc[1][0] += a1v * wv.x; acc[1][1] += a1v * wv.y; acc[1][2] += a1v * wv.z; acc[1][3] += a1v * wv.w;
        acc[2][0] += a2v * wv.x; acc[2][1] += a2v * wv.y; acc[2][2] += a2v * wv.z; acc[2][3] += a2v * wv.w;
        acc[3][0] += a3v * wv.x; acc[3][1] += a3v * wv.y; acc[3][2] += a3v * wv.z; acc[3][3] += a3v * wv.w;
    }

    // store Wh as fp16 (two half2 per row of 4 columns)
#pragma unroll
    for (int j = 0; j < 4; j++) {
        int gr = row0 + rbase + j;
        if (gr < NN) {
            __half2 p01 = __float22half2_rn(make_float2(acc[j][0], acc[j][1]));
            __half2 p23 = __float22half2_rn(make_float2(acc[j][2], acc[j][3]));
            g_Whh[gr * (OUT_F / 2) + (cbase >> 1)]     = p01;
            g_Whh[gr * (OUT_F / 2) + (cbase >> 1) + 1] = p23;
        }
    }

    // ---- fused s1/s2: s1[r] = Wh[r,:]·a[0:64], s2[r] = Wh[r,:]·a[64:128] ----
    float av1[4], av2[4];
#pragma unroll
    for (int c = 0; c < 4; c++) { av1[c] = a[cbase + c]; av2[c] = a[64 + cbase + c]; }
#pragma unroll
    for (int j = 0; j < 4; j++) {
        float p1 = acc[j][0]*av1[0] + acc[j][1]*av1[1] + acc[j][2]*av1[2] + acc[j][3]*av1[3];
        float p2 = acc[j][0]*av2[0] + acc[j][1]*av2[1] + acc[j][2]*av2[2] + acc[j][3]*av2[3];
        // xor-reduce over the 16 col-group lanes (xor of bits 0..3 stays in row group)
#pragma unroll
        for (int off = 8; off > 0; off >>= 1) {
            p1 += __shfl_xor_sync(0xFFFFFFFFu, p1, off);
            p2 += __shfl_xor_sync(0xFFFFFFFFu, p2, off);
        }
        int gr = row0 + rbase + j;
        if (tc == 0 && gr < NN) { g_s1[gr] = p1; g_s2[gr] = p2; }
    }

    // ---- fused column-sum partials (zero-degree softmax fallback) ----------
    __syncthreads();                          // done with hs: reuse as scratch
    float* cs = hs;                           // 256*4 floats = 4 KB
    {
        float4 colsum = make_float4(acc[0][0] + acc[1][0] + acc[2][0] + acc[3][0],
                                    acc[0][1] + acc[1][1] + acc[2][1] + acc[3][1],
                                    acc[0][2] + acc[1][2] + acc[2][2] + acc[3][2],
                                    acc[0][3] + acc[1][3] + acc[2][3] + acc[3][3]);
        *(float4*)&cs[t * 4] = colsum;
    }
    __syncthreads();
    if (t < 64) {
        int tcq = t >> 2, ccq = t & 3;
        float s = 0.f;
#pragma unroll
        for (int tr2 = 0; tr2 < 16; tr2++) s += cs[(tr2 * 16 + tcq) * 4 + ccq];
        g_meanpart[blockIdx.x * OUT_F + t] = s;
    }
}

// ---------------- 2. warp-per-row: 2-chunk prefetch + split-warp half4 gather
// Phase A (R16, proven): bucket ids AND s2 values for up to TWO chunks loaded
// up front; dedup/stage runs on LDS only; (w, uint2-row-base) packed float2.
// Phase B (new): lanes 0-15 take slot j, lanes 16-31 slot j+1; each lane does
// ONE LDG.64 (uint2 = 4 half columns). 16 LDG + 16 LDS per row (halved).
// Fold halves via 4x shfl_xor(16); half-warp STG.128 output.
__global__ void __launch_bounds__(256, 8) row_kernel(float* __restrict__ out) {
    __shared__ int    sc[8][CAP];             // per-warp real dst ids (dedup)  4 KB
    __shared__ float2 swc[8][CAP];            // per-warp (w, uint2 row base)   8 KB
    int wrp = threadIdx.x >> 5;
    int gtid = blockIdx.x * blockDim.x + threadIdx.x;
    int row = gtid >> 5;                      // uniform across the warp
    int lane = gtid & 31;
    if (row >= NN) return;

    int deg = g_deg[row];
    if (deg > CAP) deg = CAP;
    __syncwarp();
    if (lane == 0) g_deg[row] = 0;            // restore zero-invariant for replay

    const int* bucket = &g_cols[row * CAP];
    int*    scw  = sc[wrp];
    float2* swcw = swc[wrp];
    float s1r = g_s1[row];
    float swl = 0.f;
    int nch = (deg + 31) >> 5;

    // -------- Phase A: prefetch both chunks, then dedup + stage -------------
    bool v0 = lane < deg;
    int  c0 = v0 ? bucket[lane] : -(lane + 1);        // unique sentinels
    bool have1 = nch > 1;
    bool v1 = have1 && (32 + lane) < deg;
    int  c1 = v1 ? bucket[32 + lane] : -(lane + 33);  // distinct sentinel range
    float s20 = g_s2[c0 < 0 ? 0 : c0];
    float s21 = have1 ? g_s2[c1 < 0 ? 0 : c1] : 0.f;

    {   // ---- process chunk 0 (within-chunk dedup only) ----
        unsigned peers = __match_any_sync(0xFFFFFFFFu, c0);
        bool dup = (peers & ((1u << lane) - 1u)) != 0u;
        float w = 0.f;
        bool live = v0 && !dup;
        if (live) {
            float x = s1r + s20;
            float lr = x > 0.f ? x : ALPHA * x;       // leaky relu
            w = __expf(lr);                           // rel err ~1e-6 << budget
            swl += w;
        }
        scw[lane]  = c0;
        swcw[lane] = make_float2(w, __int_as_float(live ? c0 * 16 : 0));  // uint2 units
        __syncwarp();
    }
    if (have1) {  // ---- process chunk 1 (cross compare vs chunk 0 via LDS) ----
        bool dup = false;
        for (int q = 0; q < 32; q++)                  // break-free: pipelined LDS
            if (scw[q] == c1) dup = true;
        unsigned peers = __match_any_sync(0xFFFFFFFFu, c1);
        if (peers & ((1u << lane) - 1u)) dup = true;
        float w = 0.f;
        bool live = v1 && !dup;
        if (live) {
            float x = s1r + s21;
            float lr = x > 0.f ? x : ALPHA * x;
            w = __expf(lr);
            swl += w;
        }
        scw[32 + lane]  = c1;
        swcw[32 + lane] = make_float2(w, __int_as_float(live ? c1 * 16 : 0));
        __syncwarp();
    }
    // ---- chunks >= 2: P ~ 1e-6, serial fallback ----
    for (int ch = 2; ch < nch; ch++) {
        int p0 = ch << 5;
        int p = p0 + lane;
        bool valid = p < deg;
        int c = valid ? bucket[p] : -(lane + 1 + p0);
        float s2v = g_s2[c < 0 ? 0 : c];
        bool dup = false;
        for (int q = 0; q < p0; q++)
            if (scw[q] == c) dup = true;
        unsigned peers = __match_any_sync(0xFFFFFFFFu, c);
        if (peers & ((1u << lane) - 1u)) dup = true;
        float w = 0.f;
        bool live = valid && !dup;
        if (live) {
            float x = s1r + s2v;
            float lr = x > 0.f ? x : ALPHA * x;
            w = __expf(lr);
            swl += w;
        }
        scw[p]  = c;
        swcw[p] = make_float2(w, __int_as_float(live ? c * 16 : 0));
        __syncwarp();
    }

    // -------- Phase B: split-warp half4 gather, 2 slots / iteration ---------
    // Boundary safety: slot deg (odd deg) is always within the staged region
    // (deg odd => deg < nch*32) and carries w=0.
    int half = lane >> 4;                     // 0: slot j, 1: slot j+1
    int cl = lane & 15;                       // 4-column group
    const uint2* whh4 = (const uint2*)g_Whh;  // 8B = 4 half columns
    float4 a4 = make_float4(0.f, 0.f, 0.f, 0.f);
#pragma unroll 4
    for (int j = 0; j < deg; j += 2) {
        float2 wc = swcw[j + half];           // 2-address broadcast LDS.64
        int base = __float_as_int(wc.y);      // row base in uint2 units
        uint2 u = whh4[base + cl];            // LDG.64: cols 4cl..4cl+3
        float2 va = __half22float2(*(const __half2*)&u.x);
        float2 vb = __half22float2(*(const __half2*)&u.y);
        a4.x += wc.x * va.x;
        a4.y += wc.x * va.y;
        a4.z += wc.x * vb.x;
        a4.w += wc.x * vb.y;
    }
    // fold odd half into even half (symmetric: all lanes get the sum)
    a4.x += __shfl_xor_sync(0xFFFFFFFFu, a4.x, 16);
    a4.y += __shfl_xor_sync(0xFFFFFFFFu, a4.y, 16);
    a4.z += __shfl_xor_sync(0xFFFFFFFFu, a4.z, 16);
    a4.w += __shfl_xor_sync(0xFFFFFFFFu, a4.w, 16);

    float sw = swl;
#pragma unroll
    for (int off = 16; off > 0; off >>= 1)
        sw += __shfl_xor_sync(0xFFFFFFFFu, sw, off);

    if (deg == 0) {
        // softmax over an all -inf row is uniform -> h' = column mean of Wh
        float4 m = make_float4(0.f, 0.f, 0.f, 0.f);
        for (int b = 0; b < GEMM_BLOCKS; b++) {
            float4 mp = *(const float4*)&g_meanpart[b * OUT_F + 4 * cl];
            m.x += mp.x; m.y += mp.y; m.z += mp.z; m.w += mp.w;
        }
        float innn = 1.f / (float)NN;
        a4 = make_float4(m.x * innn, m.y * innn, m.z * innn, m.w * innn);
        sw = 1.f;
    }
    if (lane < 16) {
        float inv = 1.f / sw;
        float4 r = make_float4(elu_f(a4.x * inv), elu_f(a4.y * inv),
                               elu_f(a4.z * inv), elu_f(a4.w * inv));
        *(float4*)&out[row * OUT_F + 4 * cl] = r;   // STG.128
    }
}

// ---------------- launch ----------------------------------------------------
extern "C" void kernel_launch(void* const* d_in, const int* in_sizes, int n_in,
                              void* d_out, int out_size) {
    const float* h  = (const float*)d_in[0];
    const void*  ei = d_in[1];
    const float* W  = (const float*)d_in[2];
    const float* a  = (const float*)d_in[3];
    float* out = (float*)d_out;

    // opt into >48KB dynamic smem (idempotent, graph-capture-safe)
    cudaFuncSetAttribute(fused_kernel, cudaFuncAttributeMaxDynamicSharedMemorySize,
                         FUSED_SMEM);

    fused_kernel<<<GEMM_BLOCKS + SCAT_BLOCKS, 256, FUSED_SMEM>>>(h, W, a, ei);
    row_kernel<<<(NN * 32 + 255) / 256, 256>>>(out);
}